// round 4
// baseline (speedup 1.0000x reference)
#include <cuda_runtime.h>
#include <cuda_bf16.h>
#include <cstdint>

// ===========================================================================
// NT-Xent (SimCLR) loss, B=4096, D=256, T=0.5  ->  N=8192 rows, K=256.
//
// loss = mean_i( log( sum_{j != i} exp(2*sim_ij) ) - 2*pos_i )
// sim = Zb Zb^T with Zb = row-normalized concat(z_i, z_j) in bf16.
// sim in [-1,1] -> exp(2*sim) needs no max-tracking.
// Diagonal handled by summing ALL j and subtracting exp(2*||zb||^2) later
// (same ex2.approx formula so it cancels to rounding).
//
// NOTE: this bench compiles through a plain compute_103 virtual arch, so
// tcgen05/TMEM PTX is rejected by ptxas. Tensor path used here is
// mma.sync.m16n8k16 bf16 (fallback HMMA) + ldmatrix + cp.async.
//
// Launches:
//   1) normalize_kernel : fp32 row-normalize -> g_zb (bf16)
//   2) simexp_kernel    : 128x128x256 HMMA tiles, epilogue exp(2*S) row-sums
//                         -> g_rowpart[row][128] (deterministic pure stores)
//   3) rowloss_kernel   : reduce 128 partials/row, subtract diag, -2*pos,
//                         block partial sums
//   4) final_kernel     : deterministic reduce -> out[0]
// ===========================================================================

#define N_TOTAL 8192
#define DK      256
#define TILE    128
#define NCOLT   (N_TOTAL / TILE)       // 64 col tiles
#define NSLOTS  (NCOLT * 2)            // 128 partial slots per row

// exp(2x) = exp2(x * 2*log2(e))
#define EXP2_SCALE 2.8853900817779268f

__device__ __nv_bfloat16 g_zb[(size_t)N_TOTAL * DK];        // 4 MB
__device__ float g_rowpart[(size_t)N_TOTAL * NSLOTS];       // 4 MB
__device__ float g_partial[1024];

// ---------------------------------------------------------------------------
__device__ __forceinline__ uint32_t smem_u32(const void* p) {
    uint32_t a;
    asm("{ .reg .u64 t; cvta.to.shared.u64 t, %1; cvt.u32.u64 %0, t; }"
        : "=r"(a) : "l"(p));
    return a;
}

__device__ __forceinline__ float fast_exp2(float x) {
    float y;
    asm("ex2.approx.f32 %0, %1;" : "=f"(y) : "f"(x));
    return y;
}

#define LDSM_X4(r, addr) \
    asm volatile("ldmatrix.sync.aligned.m8n8.x4.shared.b16 {%0,%1,%2,%3}, [%4];" \
        : "=r"((r)[0]), "=r"((r)[1]), "=r"((r)[2]), "=r"((r)[3]) : "r"(addr))

#define MMA16816(c, a, b0v, b1v) \
    asm volatile("mma.sync.aligned.m16n8k16.row.col.f32.bf16.bf16.f32 " \
        "{%0,%1,%2,%3}, {%4,%5,%6,%7}, {%8,%9}, {%0,%1,%2,%3};" \
        : "+f"((c)[0]), "+f"((c)[1]), "+f"((c)[2]), "+f"((c)[3]) \
        : "r"((a)[0]), "r"((a)[1]), "r"((a)[2]), "r"((a)[3]), \
          "r"(b0v), "r"(b1v))

__device__ __forceinline__ void cp16(uint32_t saddr, const void* gptr) {
    uint64_t g;
    asm volatile("cvta.to.global.u64 %0, %1;" : "=l"(g) : "l"(gptr));
    asm volatile("cp.async.cg.shared.global [%0], [%1], 16;"
                 :: "r"(saddr), "l"(g) : "memory");
}

template <int N>
__device__ __forceinline__ void cp_wait() {
    asm volatile("cp.async.wait_group %0;" :: "n"(N) : "memory");
}
__device__ __forceinline__ void cp_commit() {
    asm volatile("cp.async.commit_group;" ::: "memory");
}

// ---------------------------------------------------------------------------
// Kernel 1: normalize rows (fp32) -> bf16
// ---------------------------------------------------------------------------
__global__ __launch_bounds__(256) void normalize_kernel(
    const float* __restrict__ zi, const float* __restrict__ zj)
{
    int row  = blockIdx.x * 8 + (threadIdx.x >> 5);
    int lane = threadIdx.x & 31;
    const float* src = (row < 4096) ? zi + (size_t)row * DK
                                    : zj + (size_t)(row - 4096) * DK;
    float v[8];
    float ss = 0.f;
    #pragma unroll
    for (int k = 0; k < 8; ++k) { v[k] = src[lane + 32 * k]; ss += v[k] * v[k]; }
    #pragma unroll
    for (int o = 16; o; o >>= 1) ss += __shfl_xor_sync(0xffffffffu, ss, o);
    float rn = rsqrtf(ss);
    #pragma unroll
    for (int k = 0; k < 8; ++k)
        g_zb[(size_t)row * DK + lane + 32 * k] = __float2bfloat16(v[k] * rn);
}

// ---------------------------------------------------------------------------
// Kernel 2: 128x128 HMMA tile GEMM + exp row-sums.
// grid (64 row tiles, 64 col tiles), 256 threads (8 warps, 4x2 warp grid,
// warp tile 32(M) x 64(N)). K=256 pipelined in 4 chunks of 64 via cp.async.
//
// SMEM per stage: A chunk 128x64 bf16 (16 KB, swizzled) + B chunk (16 KB).
// 2 stages = 64 KB -> 2 CTAs/SM.
// ---------------------------------------------------------------------------
#define KCHUNK      64
#define MAT_BYTES   (TILE * KCHUNK * 2)          // 16384
#define STAGE_BYTES (2 * MAT_BYTES)              // 32768
#define SMEM_BYTES  (2 * STAGE_BYTES)            // 65536

// swizzled byte offset within a [128 x 64 bf16] chunk: row r, 16B-group kg(0..7)
__device__ __forceinline__ uint32_t sw_off(int r, int kg) {
    return (uint32_t)(r * 128 + ((kg ^ (r & 7)) << 4));
}

__device__ __forceinline__ void prefetch_chunk(
    uint32_t sbase, int stage, int row0, int col0, int chunk, int tid)
{
    #pragma unroll
    for (int i = 0; i < 8; ++i) {
        int v   = tid + i * 256;         // 0..2047
        int mat = v >> 10;               // 0 = A, 1 = B
        int r   = (v >> 3) & 127;
        int kg  = v & 7;
        int grow = (mat ? col0 : row0) + r;
        const __nv_bfloat16* g = g_zb + (size_t)grow * DK + chunk * KCHUNK + kg * 8;
        uint32_t s = sbase + stage * STAGE_BYTES + mat * MAT_BYTES + sw_off(r, kg);
        cp16(s, g);
    }
    cp_commit();
}

__global__ __launch_bounds__(256, 2) void simexp_kernel() {
    extern __shared__ char smem[];
    const uint32_t sbase = smem_u32(smem);
    const int tid  = threadIdx.x;
    const int warp = tid >> 5;
    const int lane = tid & 31;
    const int row0 = blockIdx.x * TILE;
    const int col0 = blockIdx.y * TILE;
    const int warp_m = (warp >> 1) * 32;
    const int warp_n = (warp & 1) * 64;

    float acc[2][8][4];
    #pragma unroll
    for (int mf = 0; mf < 2; ++mf)
        #pragma unroll
        for (int nf = 0; nf < 8; ++nf)
            #pragma unroll
            for (int q = 0; q < 4; ++q) acc[mf][nf][q] = 0.f;

    prefetch_chunk(sbase, 0, row0, col0, 0, tid);

    #pragma unroll
    for (int c = 0; c < 4; ++c) {
        if (c + 1 < 4) {
            prefetch_chunk(sbase, (c + 1) & 1, row0, col0, c + 1, tid);
            cp_wait<1>();
        } else {
            cp_wait<0>();
        }
        __syncthreads();

        const uint32_t abase = sbase + (c & 1) * STAGE_BYTES;
        const uint32_t bbase = abase + MAT_BYTES;

        #pragma unroll
        for (int ks = 0; ks < 4; ++ks) {
            // A fragments: two m16 blocks
            uint32_t afr[2][4];
            #pragma unroll
            for (int mf = 0; mf < 2; ++mf) {
                int r  = warp_m + mf * 16 + (lane & 15);
                int kg = 2 * ks + (lane >> 4);
                LDSM_X4(afr[mf], abase + sw_off(r, kg));
            }
            // B fragments: four n16 blocks covering n 0..63
            uint32_t bfr[4][4];
            #pragma unroll
            for (int nb = 0; nb < 4; ++nb) {
                int n  = warp_n + nb * 16 + ((lane >> 4) << 3) + (lane & 7);
                int kg = 2 * ks + ((lane >> 3) & 1);
                LDSM_X4(bfr[nb], bbase + sw_off(n, kg));
            }
            #pragma unroll
            for (int mf = 0; mf < 2; ++mf)
                #pragma unroll
                for (int nb = 0; nb < 4; ++nb) {
                    MMA16816(acc[mf][2 * nb    ], afr[mf], bfr[nb][0], bfr[nb][1]);
                    MMA16816(acc[mf][2 * nb + 1], afr[mf], bfr[nb][2], bfr[nb][3]);
                }
        }
        __syncthreads();
    }

    // Epilogue: rs over the warp's 64 columns for this thread's 4 rows.
    // C frag: c0/c1 -> row (lane>>2), c2/c3 -> row+8, cols 2*(lane&3)+{0,1}.
    float rs[4] = {0.f, 0.f, 0.f, 0.f};
    #pragma unroll
    for (int mf = 0; mf < 2; ++mf)
        #pragma unroll
        for (int nf = 0; nf < 8; ++nf) {
            rs[mf * 2 + 0] += fast_exp2(acc[mf][nf][0] * EXP2_SCALE)
                            + fast_exp2(acc[mf][nf][1] * EXP2_SCALE);
            rs[mf * 2 + 1] += fast_exp2(acc[mf][nf][2] * EXP2_SCALE)
                            + fast_exp2(acc[mf][nf][3] * EXP2_SCALE);
        }
    // reduce over the 4 lanes sharing each row (lane&3 dimension)
    #pragma unroll
    for (int o = 1; o < 4; o <<= 1) {
        #pragma unroll
        for (int q = 0; q < 4; ++q)
            rs[q] += __shfl_xor_sync(0xffffffffu, rs[q], o);
    }
    if ((lane & 3) == 0) {
        int g    = lane >> 2;
        int slot = blockIdx.y * 2 + (warp & 1);
        g_rowpart[(size_t)(row0 + warp_m +  0 + g) * NSLOTS + slot] = rs[0];
        g_rowpart[(size_t)(row0 + warp_m +  8 + g) * NSLOTS + slot] = rs[1];
        g_rowpart[(size_t)(row0 + warp_m + 16 + g) * NSLOTS + slot] = rs[2];
        g_rowpart[(size_t)(row0 + warp_m + 24 + g) * NSLOTS + slot] = rs[3];
    }
}

// ---------------------------------------------------------------------------
// Kernel 3: per-row loss term (warp per row), block partial sums
// ---------------------------------------------------------------------------
__global__ __launch_bounds__(256) void rowloss_kernel() {
    __shared__ float wsum[8];
    int w    = threadIdx.x >> 5;
    int lane = threadIdx.x & 31;
    int row  = blockIdx.x * 8 + w;
    int prow = (row < 4096) ? row + 4096 : row - 4096;

    // sum of 128 partial exp-sums (coalesced)
    const float* pp = g_rowpart + (size_t)row * NSLOTS;
    float se = pp[lane] + pp[lane + 32] + pp[lane + 64] + pp[lane + 96];

    const __nv_bfloat16* a = g_zb + (size_t)row  * DK;
    const __nv_bfloat16* b = g_zb + (size_t)prow * DK;
    float diag = 0.f, pos = 0.f;
    #pragma unroll
    for (int k = 0; k < 8; ++k) {
        float av = __bfloat162float(a[lane + 32 * k]);
        float bv = __bfloat162float(b[lane + 32 * k]);
        diag += av * av;
        pos  += av * bv;
    }
    #pragma unroll
    for (int o = 16; o; o >>= 1) {
        se   += __shfl_xor_sync(0xffffffffu, se,   o);
        diag += __shfl_xor_sync(0xffffffffu, diag, o);
        pos  += __shfl_xor_sync(0xffffffffu, pos,  o);
    }
    if (lane == 0) {
        // subtract self-similarity with the SAME exp formula as the epilogue
        float s = se - fast_exp2(diag * EXP2_SCALE);
        wsum[w] = __logf(s) - 2.f * pos;    // lse - pos/T
    }
    __syncthreads();
    if (threadIdx.x == 0) {
        float s = 0.f;
        #pragma unroll
        for (int i = 0; i < 8; ++i) s += wsum[i];
        g_partial[blockIdx.x] = s;
    }
}

// ---------------------------------------------------------------------------
// Kernel 4: deterministic final reduction
// ---------------------------------------------------------------------------
__global__ __launch_bounds__(1024) void final_kernel(float* out) {
    __shared__ float s[1024];
    s[threadIdx.x] = g_partial[threadIdx.x];
    __syncthreads();
    #pragma unroll
    for (int o = 512; o; o >>= 1) {
        if (threadIdx.x < o) s[threadIdx.x] += s[threadIdx.x + o];
        __syncthreads();
    }
    if (threadIdx.x == 0) out[0] = s[0] * (1.0f / (float)N_TOTAL);
}

// ---------------------------------------------------------------------------
extern "C" void kernel_launch(void* const* d_in, const int* in_sizes, int n_in,
                              void* d_out, int out_size)
{
    const float* zi = (const float*)d_in[0];
    const float* zj = (const float*)d_in[1];
    float* out = (float*)d_out;

    cudaFuncSetAttribute(simexp_kernel,
                         cudaFuncAttributeMaxDynamicSharedMemorySize, SMEM_BYTES);

    normalize_kernel<<<1024, 256>>>(zi, zj);
    simexp_kernel<<<dim3(NCOLT, NCOLT), 256, SMEM_BYTES>>>();
    rowloss_kernel<<<1024, 256>>>();
    final_kernel<<<1, 1024>>>(out);
}

// round 5
// speedup vs baseline: 1.5402x; 1.5402x over previous
#include <cuda_runtime.h>
#include <cuda_bf16.h>
#include <cstdint>

// ===========================================================================
// NT-Xent (SimCLR) loss, B=4096, D=256, T=0.5  ->  N=8192 rows, K=256.
//
// loss = mean_i( log( sum_{j != i} exp(2*sim_ij) ) - 2*pos_i )
//
// R4: exploit exp(2*sim) symmetry -- compute only the 2080 upper-triangle
// 128x128 tiles; each off-diagonal tile emits BOTH row-sums (for block x)
// and column-sums (for block y). Logit scale folded into the bf16 inputs:
// zb = z_hat * sqrt(2*log2 e), so epilogue exp is a bare ex2.approx(acc).
//
// tcgen05 is unreachable (plain compute_103 vtarget), so the tensor path is
// mma.sync.m16n8k16 bf16 + ldmatrix + cp.async (2-stage K pipeline).
//
// Launches:
//   1) normalize_kernel : fp32 row-normalize * SCALE_S -> g_zb (bf16)
//   2) simexp_kernel    : 2080 triangle tiles; row+col exp-sums ->
//                         g_rowpart[row][128] (deterministic pure stores)
//   3) rowloss_kernel   : reduce 128 partials/row, subtract diag, - pos*ln2
//   4) final_kernel     : deterministic reduce -> out[0]
// ===========================================================================

#define N_TOTAL 8192
#define DK      256
#define TILE    128
#define NTILES  64                     // 64 row/col blocks
#define NSLOTS  (NTILES * 2)           // 128 partial slots per row
#define NTRI    (NTILES * (NTILES + 1) / 2)   // 2080 triangle tiles

// sqrt(2*log2(e)) : fold exp(2x)=exp2(2*log2e*x) scale into the inputs
#define SCALE_S 1.6986435987381852f

__device__ __nv_bfloat16 g_zb[(size_t)N_TOTAL * DK];        // 4 MB
__device__ float g_rowpart[(size_t)N_TOTAL * NSLOTS];       // 4 MB
__device__ float g_partial[1024];

// ---------------------------------------------------------------------------
__device__ __forceinline__ uint32_t smem_u32(const void* p) {
    uint32_t a;
    asm("{ .reg .u64 t; cvta.to.shared.u64 t, %1; cvt.u32.u64 %0, t; }"
        : "=r"(a) : "l"(p));
    return a;
}

__device__ __forceinline__ float fast_exp2(float x) {
    float y;
    asm("ex2.approx.f32 %0, %1;" : "=f"(y) : "f"(x));
    return y;
}

#define LDSM_X4(r, addr) \
    asm volatile("ldmatrix.sync.aligned.m8n8.x4.shared.b16 {%0,%1,%2,%3}, [%4];" \
        : "=r"((r)[0]), "=r"((r)[1]), "=r"((r)[2]), "=r"((r)[3]) : "r"(addr))

#define MMA16816(c, a, b0v, b1v) \
    asm volatile("mma.sync.aligned.m16n8k16.row.col.f32.bf16.bf16.f32 " \
        "{%0,%1,%2,%3}, {%4,%5,%6,%7}, {%8,%9}, {%0,%1,%2,%3};" \
        : "+f"((c)[0]), "+f"((c)[1]), "+f"((c)[2]), "+f"((c)[3]) \
        : "r"((a)[0]), "r"((a)[1]), "r"((a)[2]), "r"((a)[3]), \
          "r"(b0v), "r"(b1v))

__device__ __forceinline__ void cp16(uint32_t saddr, const void* gptr) {
    uint64_t g;
    asm volatile("cvta.to.global.u64 %0, %1;" : "=l"(g) : "l"(gptr));
    asm volatile("cp.async.cg.shared.global [%0], [%1], 16;"
                 :: "r"(saddr), "l"(g) : "memory");
}

template <int N>
__device__ __forceinline__ void cp_wait() {
    asm volatile("cp.async.wait_group %0;" :: "n"(N) : "memory");
}
__device__ __forceinline__ void cp_commit() {
    asm volatile("cp.async.commit_group;" ::: "memory");
}

// ---------------------------------------------------------------------------
// Kernel 1: normalize rows (fp32) -> bf16, pre-scaled by SCALE_S
// ---------------------------------------------------------------------------
__global__ __launch_bounds__(256) void normalize_kernel(
    const float* __restrict__ zi, const float* __restrict__ zj)
{
    int row  = blockIdx.x * 8 + (threadIdx.x >> 5);
    int lane = threadIdx.x & 31;
    const float* src = (row < 4096) ? zi + (size_t)row * DK
                                    : zj + (size_t)(row - 4096) * DK;
    float v[8];
    float ss = 0.f;
    #pragma unroll
    for (int k = 0; k < 8; ++k) { v[k] = src[lane + 32 * k]; ss += v[k] * v[k]; }
    #pragma unroll
    for (int o = 16; o; o >>= 1) ss += __shfl_xor_sync(0xffffffffu, ss, o);
    float rn = rsqrtf(ss) * SCALE_S;
    #pragma unroll
    for (int k = 0; k < 8; ++k)
        g_zb[(size_t)row * DK + lane + 32 * k] = __float2bfloat16(v[k] * rn);
}

// ---------------------------------------------------------------------------
// Kernel 2: upper-triangle 128x128 HMMA tiles + exp row/col sums.
// 1D grid of 2080 CTAs; CTA t -> tile (x, y), y >= x.
// 256 threads (8 warps, 4(M) x 2(N) warp grid, warp tile 32x64).
// K=256 pipelined in 4 chunks of 64 via cp.async, 2 stages (64 KB smem).
// ---------------------------------------------------------------------------
#define KCHUNK      64
#define MAT_BYTES   (TILE * KCHUNK * 2)          // 16384
#define STAGE_BYTES (2 * MAT_BYTES)              // 32768
#define SMEM_BYTES  (2 * STAGE_BYTES)            // 65536

// swizzled byte offset within a [128 x 64 bf16] chunk: row r, 16B-group kg(0..7)
__device__ __forceinline__ uint32_t sw_off(int r, int kg) {
    return (uint32_t)(r * 128 + ((kg ^ (r & 7)) << 4));
}

__device__ __forceinline__ void prefetch_chunk(
    uint32_t sbase, int stage, int row0, int col0, int chunk, int tid)
{
    #pragma unroll
    for (int i = 0; i < 8; ++i) {
        int v   = tid + i * 256;         // 0..2047
        int mat = v >> 10;               // 0 = A, 1 = B
        int r   = (v >> 3) & 127;
        int kg  = v & 7;
        int grow = (mat ? col0 : row0) + r;
        const __nv_bfloat16* g = g_zb + (size_t)grow * DK + chunk * KCHUNK + kg * 8;
        uint32_t s = sbase + stage * STAGE_BYTES + mat * MAT_BYTES + sw_off(r, kg);
        cp16(s, g);
    }
    cp_commit();
}

__global__ __launch_bounds__(256, 2) void simexp_kernel() {
    extern __shared__ char smem[];
    const uint32_t sbase = smem_u32(smem);
    const int tid  = threadIdx.x;
    const int warp = tid >> 5;
    const int lane = tid & 31;

    // --- decode linear tile id -> (x, y) with y >= x; start(x)=x*(129-x)/2 ---
    const int t = blockIdx.x;
    int x = __float2int_rd((129.0f - sqrtf(16641.0f - 8.0f * (float)t)) * 0.5f);
    if (x > 63) x = 63;
    while (x > 0 && x * (129 - x) / 2 > t) --x;
    while ((x + 1) * (129 - (x + 1)) / 2 <= t) ++x;
    const int y = x + (t - x * (129 - x) / 2);

    const int row0 = x * TILE;
    const int col0 = y * TILE;
    const int warp_m = (warp >> 1) * 32;
    const int warp_n = (warp & 1) * 64;

    float acc[2][8][4];
    #pragma unroll
    for (int mf = 0; mf < 2; ++mf)
        #pragma unroll
        for (int nf = 0; nf < 8; ++nf)
            #pragma unroll
            for (int q = 0; q < 4; ++q) acc[mf][nf][q] = 0.f;

    prefetch_chunk(sbase, 0, row0, col0, 0, tid);

    #pragma unroll
    for (int c = 0; c < 4; ++c) {
        if (c + 1 < 4) {
            prefetch_chunk(sbase, (c + 1) & 1, row0, col0, c + 1, tid);
            cp_wait<1>();
        } else {
            cp_wait<0>();
        }
        __syncthreads();

        const uint32_t abase = sbase + (c & 1) * STAGE_BYTES;
        const uint32_t bbase = abase + MAT_BYTES;

        #pragma unroll
        for (int ks = 0; ks < 4; ++ks) {
            uint32_t afr[2][4];
            #pragma unroll
            for (int mf = 0; mf < 2; ++mf) {
                int r  = warp_m + mf * 16 + (lane & 15);
                int kg = 2 * ks + (lane >> 4);
                LDSM_X4(afr[mf], abase + sw_off(r, kg));
            }
            uint32_t bfr[4][4];
            #pragma unroll
            for (int nb = 0; nb < 4; ++nb) {
                int n  = warp_n + nb * 16 + ((lane >> 4) << 3) + (lane & 7);
                int kg = 2 * ks + ((lane >> 3) & 1);
                LDSM_X4(bfr[nb], bbase + sw_off(n, kg));
            }
            #pragma unroll
            for (int mf = 0; mf < 2; ++mf)
                #pragma unroll
                for (int nb = 0; nb < 4; ++nb) {
                    MMA16816(acc[mf][2 * nb    ], afr[mf], bfr[nb][0], bfr[nb][1]);
                    MMA16816(acc[mf][2 * nb + 1], afr[mf], bfr[nb][2], bfr[nb][3]);
                }
        }
        __syncthreads();
    }

    // --- Epilogue ---
    // C frag (mf,nf): rows warp_m+mf*16+(lane>>2)+{0,8}, cols warp_n+nf*8+2*(lane&3)+{0,1}
    float rs[4] = {0.f, 0.f, 0.f, 0.f};   // per-thread row partials (2 rows x 2 mf)
    float cs[8][2];                        // per-thread col partials (8 nf x 2 cols)
    #pragma unroll
    for (int nf = 0; nf < 8; ++nf) { cs[nf][0] = 0.f; cs[nf][1] = 0.f; }

    #pragma unroll
    for (int mf = 0; mf < 2; ++mf)
        #pragma unroll
        for (int nf = 0; nf < 8; ++nf) {
            float e0 = fast_exp2(acc[mf][nf][0]);
            float e1 = fast_exp2(acc[mf][nf][1]);
            float e2 = fast_exp2(acc[mf][nf][2]);
            float e3 = fast_exp2(acc[mf][nf][3]);
            rs[mf * 2 + 0] += e0 + e1;
            rs[mf * 2 + 1] += e2 + e3;
            cs[nf][0] += e0 + e2;
            cs[nf][1] += e1 + e3;
        }

    // row sums: reduce over lane&3 (the 4 column-lanes per row)
    #pragma unroll
    for (int o = 1; o < 4; o <<= 1)
        #pragma unroll
        for (int q = 0; q < 4; ++q)
            rs[q] += __shfl_xor_sync(0xffffffffu, rs[q], o);
    if ((lane & 3) == 0) {
        int g    = lane >> 2;
        int slot = 2 * y + (warp & 1);
        g_rowpart[(size_t)(row0 + warp_m +  0 + g) * NSLOTS + slot] = rs[0];
        g_rowpart[(size_t)(row0 + warp_m +  8 + g) * NSLOTS + slot] = rs[1];
        g_rowpart[(size_t)(row0 + warp_m + 16 + g) * NSLOTS + slot] = rs[2];
        g_rowpart[(size_t)(row0 + warp_m + 24 + g) * NSLOTS + slot] = rs[3];
    }

    // column sums (off-diagonal tiles only): contribute to rows of block y
    if (x != y) {
        // reduce over lane>>2 (the 8 row-groups per warp)
        #pragma unroll
        for (int o = 4; o < 32; o <<= 1)
            #pragma unroll
            for (int nf = 0; nf < 8; ++nf) {
                cs[nf][0] += __shfl_xor_sync(0xffffffffu, cs[nf][0], o);
                cs[nf][1] += __shfl_xor_sync(0xffffffffu, cs[nf][1], o);
            }
        float* cw = reinterpret_cast<float*>(smem);   // 8 warps x 64 cols = 2 KB
        if (lane < 4) {
            #pragma unroll
            for (int nf = 0; nf < 8; ++nf) {
                cw[warp * 64 + nf * 8 + 2 * lane    ] = cs[nf][0];
                cw[warp * 64 + nf * 8 + 2 * lane + 1] = cs[nf][1];
            }
        }
        __syncthreads();
        // 256 threads: (m-half pair, n-half, col) -> one slot value each.
        // warps {h, h+2} cover m rows 0..63 -> slot 2x; {h+4, h+6} -> slot 2x+1.
        int j  = tid & 63;
        int h  = (tid >> 6) & 1;
        int mp = tid >> 7;
        float v = cw[(h + 4 * mp) * 64 + j] + cw[(h + 4 * mp + 2) * 64 + j];
        g_rowpart[(size_t)(col0 + h * 64 + j) * NSLOTS + (2 * x + mp)] = v;
    }
}

// ---------------------------------------------------------------------------
// Kernel 3: per-row loss term (warp per row), block partial sums
// ---------------------------------------------------------------------------
__global__ __launch_bounds__(256) void rowloss_kernel() {
    __shared__ float wsum[8];
    int w    = threadIdx.x >> 5;
    int lane = threadIdx.x & 31;
    int row  = blockIdx.x * 8 + w;
    int prow = (row < 4096) ? row + 4096 : row - 4096;

    // sum of 128 partial exp-sums (coalesced)
    const float* pp = g_rowpart + (size_t)row * NSLOTS;
    float se = pp[lane] + pp[lane + 32] + pp[lane + 64] + pp[lane + 96];

    const __nv_bfloat16* a = g_zb + (size_t)row  * DK;
    const __nv_bfloat16* b = g_zb + (size_t)prow * DK;
    float diag = 0.f, pos = 0.f;                 // both in scaled units
    #pragma unroll
    for (int k = 0; k < 8; ++k) {
        float av = __bfloat162float(a[lane + 32 * k]);
        float bv = __bfloat162float(b[lane + 32 * k]);
        diag += av * av;
        pos  += av * bv;
    }
    #pragma unroll
    for (int o = 16; o; o >>= 1) {
        se   += __shfl_xor_sync(0xffffffffu, se,   o);
        diag += __shfl_xor_sync(0xffffffffu, diag, o);
        pos  += __shfl_xor_sync(0xffffffffu, pos,  o);
    }
    if (lane == 0) {
        // subtract self-similarity with the SAME exp formula as the epilogue;
        // pos is scaled by 2*log2e, so 2*pos (unscaled) = pos_scaled * ln2.
        float sv = se - fast_exp2(diag);
        wsum[w] = __logf(sv) - pos * 0.6931471805599453f;
    }
    __syncthreads();
    if (threadIdx.x == 0) {
        float s = 0.f;
        #pragma unroll
        for (int i = 0; i < 8; ++i) s += wsum[i];
        g_partial[blockIdx.x] = s;
    }
}

// ---------------------------------------------------------------------------
// Kernel 4: deterministic final reduction
// ---------------------------------------------------------------------------
__global__ __launch_bounds__(1024) void final_kernel(float* out) {
    __shared__ float s[1024];
    s[threadIdx.x] = g_partial[threadIdx.x];
    __syncthreads();
    #pragma unroll
    for (int o = 512; o; o >>= 1) {
        if (threadIdx.x < o) s[threadIdx.x] += s[threadIdx.x + o];
        __syncthreads();
    }
    if (threadIdx.x == 0) out[0] = s[0] * (1.0f / (float)N_TOTAL);
}

// ---------------------------------------------------------------------------
extern "C" void kernel_launch(void* const* d_in, const int* in_sizes, int n_in,
                              void* d_out, int out_size)
{
    const float* zi = (const float*)d_in[0];
    const float* zj = (const float*)d_in[1];
    float* out = (float*)d_out;

    cudaFuncSetAttribute(simexp_kernel,
                         cudaFuncAttributeMaxDynamicSharedMemorySize, SMEM_BYTES);

    normalize_kernel<<<1024, 256>>>(zi, zj);
    simexp_kernel<<<NTRI, 256, SMEM_BYTES>>>();
    rowloss_kernel<<<1024, 256>>>();
    final_kernel<<<1, 1024>>>(out);
}